// round 2
// baseline (speedup 1.0000x reference)
#include <cuda_runtime.h>
#include <math.h>

#define B_TOT   4096
#define NOBJ    64
#define DOBJ    32
#define FEAT    31
#define HID     256
#define OBS_W   2304
#define OTH_OFF 2048
#define NHEAD   4
#define HDIM    64
#define PITCH   260   // float pitch: mult of 4 (16B align), mod 32 = 4 (bank skew)

typedef unsigned long long ull;

__device__ __forceinline__ ull pack2(float lo, float hi) {
    ull r; asm("mov.b64 %0,{%1,%2};" : "=l"(r) : "f"(lo), "f"(hi)); return r;
}
__device__ __forceinline__ float2 unpack2(ull v) {
    float2 f; asm("mov.b64 {%0,%1},%2;" : "=f"(f.x), "=f"(f.y) : "l"(v)); return f;
}
__device__ __forceinline__ ull ffma2(ull a, ull b, ull c) {
    ull d; asm("fma.rn.f32x2 %0,%1,%2,%3;" : "=l"(d) : "l"(a), "l"(b), "l"(c)); return d;
}

struct SmemLayout {
    float feats[NOBJ * DOBJ];     // objs raw; [n*32 + d], d=31 is mask
    float A[NOBJ * PITCH];        // H1, then rawP
    float Bf[NOBJ * PITCH];       // H2
    float v0[HID];
    float v1[HID];
    float qt[HID];
    float qb[NHEAD];
    float mask[NOBJ];
    float logit[NHEAD * NOBJ];
    float wgt[NHEAD * NOBJ];
    float Th[NHEAD];
    float Svec[NHEAD * HDIM];
};

// 64x256 GEMM tile: thread owns cols {2*j2, 2*j2+1} and rows r0..r0+15.
// Packed f32x2 accumulation along K; weight prefetch double-buffered.
template<int KIN, int PIN, bool RELU>
__device__ __forceinline__ void obj_gemm2(const float* __restrict__ W,
                                          const float* __restrict__ bias,
                                          const float* sIn, float* sOut,
                                          int j2, int r0)
{
    constexpr int NC = KIN / 4;
    const int j0 = 2 * j2;
    const float2* __restrict__ Wp = reinterpret_cast<const float2*>(W);  // [k*128 + j2]
    ull acc0[16], acc1[16];
    {
        const ull b0 = pack2(bias[j0],     0.0f);
        const ull b1 = pack2(bias[j0 + 1], 0.0f);
#pragma unroll
        for (int r = 0; r < 16; r++) { acc0[r] = b0; acc1[r] = b1; }
    }
    const float* base = sIn + r0 * PIN;

    float2 c0 = Wp[0 * 128 + j2];
    float2 c1 = Wp[1 * 128 + j2];
    float2 c2 = Wp[2 * 128 + j2];
    float2 c3 = Wp[3 * 128 + j2];

    for (int c = 0; c < NC; c++) {
        const int kn = (c + 1 < NC) ? (c + 1) * 4 : c * 4;
        float2 n0 = Wp[(kn + 0) * 128 + j2];
        float2 n1 = Wp[(kn + 1) * 128 + j2];
        float2 n2 = Wp[(kn + 2) * 128 + j2];
        float2 n3 = Wp[(kn + 3) * 128 + j2];

        const ull wA0 = pack2(c0.x, c1.x);   // col j0,   k pair (4c, 4c+1)
        const ull wB0 = pack2(c0.y, c1.y);   // col j0+1, k pair (4c, 4c+1)
        const ull wA1 = pack2(c2.x, c3.x);   // col j0,   k pair (4c+2, 4c+3)
        const ull wB1 = pack2(c2.y, c3.y);
        const float* p = base + 4 * c;
#pragma unroll
        for (int r = 0; r < 16; r++) {
            const ulonglong2 v = *reinterpret_cast<const ulonglong2*>(p + r * PIN);
            acc0[r] = ffma2(v.x, wA0, acc0[r]);
            acc1[r] = ffma2(v.x, wB0, acc1[r]);
            acc0[r] = ffma2(v.y, wA1, acc0[r]);
            acc1[r] = ffma2(v.y, wB1, acc1[r]);
        }
        c0 = n0; c1 = n1; c2 = n2; c3 = n3;
    }

    if constexpr (KIN % 4 == 3) {   // remainder k = 4*NC, +1, +2 (FEAT=31)
        const int kk = 4 * NC;
        const float2 w0 = Wp[(kk + 0) * 128 + j2];
        const float2 w1 = Wp[(kk + 1) * 128 + j2];
        const float2 w2 = Wp[(kk + 2) * 128 + j2];
        const ull wA = pack2(w0.x, w1.x);
        const ull wB = pack2(w0.y, w1.y);
#pragma unroll
        for (int r = 0; r < 16; r++) {
            const ull v = *reinterpret_cast<const ull*>(base + r * PIN + kk);
            acc0[r] = ffma2(v, wA, acc0[r]);
            acc1[r] = ffma2(v, wB, acc1[r]);
            const float xv = base[r * PIN + kk + 2];
            const float2 a0 = unpack2(acc0[r]);
            const float2 a1 = unpack2(acc1[r]);
            float x0 = a0.x + a0.y + xv * w2.x;
            float x1 = a1.x + a1.y + xv * w2.y;
            if (RELU) { x0 = fmaxf(x0, 0.0f); x1 = fmaxf(x1, 0.0f); }
            *reinterpret_cast<float2*>(&sOut[(r0 + r) * PITCH + j0]) = make_float2(x0, x1);
        }
    } else {
#pragma unroll
        for (int r = 0; r < 16; r++) {
            const float2 a0 = unpack2(acc0[r]);
            const float2 a1 = unpack2(acc1[r]);
            float x0 = a0.x + a0.y;
            float x1 = a1.x + a1.y;
            if (RELU) { x0 = fmaxf(x0, 0.0f); x1 = fmaxf(x1, 0.0f); }
            *reinterpret_cast<float2*>(&sOut[(r0 + r) * PITCH + j0]) = make_float2(x0, x1);
        }
    }
}

// 256->256 GEMV with packed f32x2 accumulation.
__device__ __forceinline__ float gemv256_x2(const float* __restrict__ W, float bias,
                                            const float* sv, int j)
{
    ull acc = pack2(bias, 0.0f);
#pragma unroll 4
    for (int k = 0; k < HID; k += 4) {
        const ulonglong2 v = *reinterpret_cast<const ulonglong2*>(sv + k);
        const float w0 = W[(k + 0) * HID + j];
        const float w1 = W[(k + 1) * HID + j];
        const float w2 = W[(k + 2) * HID + j];
        const float w3 = W[(k + 3) * HID + j];
        acc = ffma2(v.x, pack2(w0, w1), acc);
        acc = ffma2(v.y, pack2(w2, w3), acc);
    }
    const float2 a = unpack2(acc);
    return a.x + a.y;
}

__global__ void __launch_bounds__(512, 1) pinet_kernel(
    const float* __restrict__ obs,
    const float* __restrict__ oW1, const float* __restrict__ ob1,
    const float* __restrict__ oW2, const float* __restrict__ ob2,
    const float* __restrict__ pW1, const float* __restrict__ pb1,
    const float* __restrict__ pW2, const float* __restrict__ pb2,
    const float* __restrict__ pW3, const float* __restrict__ pb3,
    const float* __restrict__ Wq,  const float* __restrict__ bq,
    const float* __restrict__ Wk,  const float* __restrict__ bk,
    const float* __restrict__ Wv,  const float* __restrict__ bv,
    float* __restrict__ out)
{
    extern __shared__ float smraw[];
    SmemLayout* s = reinterpret_cast<SmemLayout*>(smraw);

    const int b   = blockIdx.x;
    const int tid = threadIdx.x;
    const float* row = obs + (size_t)b * OBS_W;

    // ---- load objects (2048 floats across 512 threads) + others (256) ----
    {
        const float4* r4 = reinterpret_cast<const float4*>(row);
        reinterpret_cast<float4*>(s->feats)[tid] = r4[tid];
        if (tid < HID) s->v0[tid] = row[OTH_OFF + tid];
    }
    __syncthreads();
    if (tid < NOBJ) s->mask[tid] = s->feats[tid * DOBJ + (DOBJ - 1)];

    // ================= Stage A: per-sample path (threads 0..255) =================
    if (tid < HID) s->v1[tid] = fmaxf(gemv256_x2(oW1, ob1[tid], s->v0, tid), 0.0f);
    __syncthreads();
    if (tid < HID) {
        const float a = gemv256_x2(oW2, ob2[tid], s->v1, tid);
        out[(size_t)b * 512 + tid] = a;
        s->v0[tid] = a;
    }
    __syncthreads();
    if (tid < HID) s->v1[tid] = gemv256_x2(Wq, bq[tid], s->v0, tid);   // q, head-major
    __syncthreads();
    if (tid < HID) {
        // qt[h*64+d] = Wk[h,d,:] . q[h,:] ;  qb[h] = q[h,:] . bk[h,:]
        const int h = tid >> 6, d = tid & 63;
        const float4* wk4 = reinterpret_cast<const float4*>(Wk + h * (HDIM * HDIM) + d * HDIM);
        const float4* q4  = reinterpret_cast<const float4*>(s->v1 + h * HDIM);
        float t = 0.0f;
#pragma unroll
        for (int e = 0; e < HDIM / 4; e++) {
            const float4 w = wk4[e];
            const float4 qv = q4[e];
            t += w.x * qv.x + w.y * qv.y + w.z * qv.z + w.w * qv.w;
        }
        s->qt[tid] = t;
        if (tid < NHEAD) {
            float sb = 0.0f;
            for (int e = 0; e < HDIM; e++) sb += s->v1[tid * HDIM + e] * bk[tid * HDIM + e];
            s->qb[tid] = sb;
        }
    }
    __syncthreads();

    // ================= Stage B: per-object MLP (the big FLOPs) =================
    const int j2 = tid & 127;          // column pair
    const int r0 = (tid >> 7) * 16;    // row group of 16
    obj_gemm2<FEAT, DOBJ,  true >(pW1, pb1, s->feats, s->A,  j2, r0);
    __syncthreads();
    obj_gemm2<HID,  PITCH, true >(pW2, pb2, s->A,     s->Bf, j2, r0);
    __syncthreads();
    obj_gemm2<HID,  PITCH, false>(pW3, pb3, s->Bf,    s->A,  j2, r0);
    __syncthreads();

    // ================= Stage C: attention (q-len 1; K/V folded) =================
    const int h = (tid >> 6) & 3;
    const int n = tid & 63;
    if (tid < 256) {
        const float* rp = s->A + n * PITCH + h * HDIM;
        const float* qt = s->qt + h * HDIM;
        float dot = 0.0f;
#pragma unroll
        for (int d = 0; d < HDIM; d += 4) {
            const float4 a4 = *reinterpret_cast<const float4*>(&rp[d]);
            const float4 b4 = *reinterpret_cast<const float4*>(&qt[d]);
            dot += a4.x * b4.x + a4.y * b4.y + a4.z * b4.z + a4.w * b4.w;
        }
        const float m = s->mask[n];
        float lg = fmaf(m, dot, s->qb[h]) * 0.0625f;   // / sqrt(256)
        if (m == 0.0f) lg = -1000000000.0f;
        s->logit[h * NOBJ + n] = lg;
    }
    __syncthreads();

    {   // softmax per head; wgt = attn*mask^2, Th = sum attn*mask
        const int wid = tid >> 5, lane = tid & 31;
        if (wid < NHEAD) {
            const int hh = wid;
            const float x0 = s->logit[hh * NOBJ + lane];
            const float x1 = s->logit[hh * NOBJ + 32 + lane];
            float mx = fmaxf(x0, x1);
#pragma unroll
            for (int o = 16; o > 0; o >>= 1) mx = fmaxf(mx, __shfl_xor_sync(0xffffffffu, mx, o));
            const float e0 = expf(x0 - mx);
            const float e1 = expf(x1 - mx);
            float sum = e0 + e1;
#pragma unroll
            for (int o = 16; o > 0; o >>= 1) sum += __shfl_xor_sync(0xffffffffu, sum, o);
            const float inv = 1.0f / sum;
            const float a0 = e0 * inv, a1 = e1 * inv;
            const float m0 = s->mask[lane], m1 = s->mask[32 + lane];
            s->wgt[hh * NOBJ + lane]      = a0 * m0 * m0;
            s->wgt[hh * NOBJ + 32 + lane] = a1 * m1 * m1;
            float tt = a0 * m0 + a1 * m1;
#pragma unroll
            for (int o = 16; o > 0; o >>= 1) tt += __shfl_xor_sync(0xffffffffu, tt, o);
            if (lane == 0) s->Th[hh] = tt;
        }
    }
    __syncthreads();

    if (tid < 256) {
        // Svec[h,d] = sum_n wgt[h,n] * rawP[n, h*64+d]
        const int d = tid & 63;
        const float* wp = s->wgt + h * NOBJ;
        float acc = 0.0f;
#pragma unroll 4
        for (int nn = 0; nn < NOBJ; nn++)
            acc = fmaf(wp[nn], s->A[nn * PITCH + h * HDIM + d], acc);
        s->Svec[tid] = acc;
    }
    __syncthreads();

    if (tid < 256) {
        // out_emb[h,e] = Svec[h,:] @ Wv[h] + Th[h]*bv[h,e]
        const int e = tid & 63;
        float o = s->Th[h] * bv[h * HDIM + e];
        const float* sv = s->Svec + h * HDIM;
        const float* wv = Wv + h * (HDIM * HDIM) + e;
#pragma unroll 4
        for (int d = 0; d < HDIM; d++)
            o = fmaf(sv[d], wv[d * HDIM], o);
        out[(size_t)b * 512 + 256 + h * HDIM + e] = o;
    }
}

extern "C" void kernel_launch(void* const* d_in, const int* in_sizes, int n_in,
                              void* d_out, int out_size)
{
    const float* obs = (const float*)d_in[0];
    const float* oW1 = (const float*)d_in[1];
    const float* ob1 = (const float*)d_in[2];
    const float* oW2 = (const float*)d_in[3];
    const float* ob2 = (const float*)d_in[4];
    const float* pW1 = (const float*)d_in[5];
    const float* pb1 = (const float*)d_in[6];
    const float* pW2 = (const float*)d_in[7];
    const float* pb2 = (const float*)d_in[8];
    const float* pW3 = (const float*)d_in[9];
    const float* pb3 = (const float*)d_in[10];
    const float* Wq  = (const float*)d_in[11];
    const float* bq  = (const float*)d_in[12];
    const float* Wk  = (const float*)d_in[13];
    const float* bk  = (const float*)d_in[14];
    const float* Wv  = (const float*)d_in[15];
    const float* bv  = (const float*)d_in[16];
    float* out = (float*)d_out;

    const int smem = (int)sizeof(SmemLayout);
    cudaFuncSetAttribute(pinet_kernel, cudaFuncAttributeMaxDynamicSharedMemorySize, smem);
    pinet_kernel<<<B_TOT, 512, smem>>>(obs, oW1, ob1, oW2, ob2,
                                       pW1, pb1, pW2, pb2, pW3, pb3,
                                       Wq, bq, Wk, bk, Wv, bv, out);
}